// round 10
// baseline (speedup 1.0000x reference)
#include <cuda_runtime.h>

typedef unsigned long long u64;

// ---- packed f32x2 helpers (sm_103a packed fp32 pipe) ----
__device__ __forceinline__ u64 pk2(float l, float h) {
    u64 r; asm("mov.b64 %0, {%1,%2};" : "=l"(r) : "f"(l), "f"(h)); return r;
}
__device__ __forceinline__ u64 pkb(float w) { return pk2(w, w); }
__device__ __forceinline__ void upk(u64 v, float& l, float& h) {
    asm("mov.b64 {%0,%1}, %2;" : "=f"(l), "=f"(h) : "l"(v));
}
__device__ __forceinline__ u64 fma2(u64 a, u64 b, u64 c) {
    u64 d; asm("fma.rn.f32x2 %0, %1, %2, %3;" : "=l"(d) : "l"(a), "l"(b), "l"(c)); return d;
}
__device__ __forceinline__ u64 add2(u64 a, u64 b) {
    u64 d; asm("add.rn.f32x2 %0, %1, %2;" : "=l"(d) : "l"(a), "l"(b)); return d;
}
__device__ __forceinline__ u64 mul2(u64 a, u64 b) {
    u64 d; asm("mul.rn.f32x2 %0, %1, %2;" : "=l"(d) : "l"(a), "l"(b)); return d;
}

#define KDUP(bits) ((((u64)(bits)) << 32) | (u64)(bits))
static constexpr u64 K06  = KDUP(0x3F19999Au);  // 0.6f
static constexpr u64 K04  = KDUP(0x3ECCCCCDu);  // 0.4f
static constexpr u64 KABS = 0x7FFFFFFF7FFFFFFFull;

// leaky_relu(x, 0.2) == 0.6*x + 0.4*|x|
__device__ __forceinline__ u64 leaky2(u64 v) {
    return fma2(v & KABS, K04, mul2(v, K06));
}

// HW tanh: 1 MUFU per scalar
__device__ __forceinline__ u64 tanh2(u64 v) {
    float l, h; upk(v, l, h);
    float tl, th;
    asm("tanh.approx.f32 %0, %1;" : "=f"(tl) : "f"(l));
    asm("tanh.approx.f32 %0, %1;" : "=f"(th) : "f"(h));
    return pk2(tl, th);
}

__global__ void __launch_bounds__(128, 4)
minigen_kernel(const float4* __restrict__ x,
               const float* __restrict__ w_enc1, const float* __restrict__ b_enc1,
               const float* __restrict__ w_bneck, const float* __restrict__ b_bneck,
               const float* __restrict__ w_dec1, const float* __restrict__ b_dec1,
               const float* __restrict__ w_out,  const float* __restrict__ b_out,
               float4* __restrict__ out)
{
    // all weights stored PRE-DUPLICATED as u64 -> single LDS.64 per use
    __shared__ u64 s_we[24], s_be[4];
    __shared__ u64 s_wb[96], s_bb[8];
    __shared__ u64 s_wdf[128], s_bd[4];   // dec1 folded: {w0, w2, w0+w1, w1+w2} per (c,ci)
    __shared__ u64 s_wof[32],  s_bo[2];   // out  folded

    int t = threadIdx.x;
    if (t < 24) s_we[t] = pkb(w_enc1[t]);
    if (t < 96) s_wb[t] = pkb(w_bneck[t]);
    if (t < 4)  { s_be[t] = pkb(b_enc1[t]); s_bd[t] = pkb(b_dec1[t]); }
    if (t < 8)  s_bb[t] = pkb(b_bneck[t]);
    if (t < 2)  s_bo[t] = pkb(b_out[t]);
    if (t < 32) {   // dec1 fold: t = c*8 + ci
        float w0 = w_dec1[t*3], w1 = w_dec1[t*3+1], w2 = w_dec1[t*3+2];
        s_wdf[t*4+0] = pkb(w0);      s_wdf[t*4+1] = pkb(w2);
        s_wdf[t*4+2] = pkb(w0 + w1); s_wdf[t*4+3] = pkb(w1 + w2);
    }
    if (t < 8) {    // out fold: t = c*4 + ci
        float w0 = w_out[t*3], w1 = w_out[t*3+1], w2 = w_out[t*3+2];
        s_wof[t*4+0] = pkb(w0);      s_wof[t*4+1] = pkb(w2);
        s_wof[t*4+2] = pkb(w0 + w1); s_wof[t*4+3] = pkb(w1 + w2);
    }
    __syncthreads();

    int i = blockIdx.x * blockDim.x + threadIdx.x;   // sample-pair index
    const float4* xp = x + (size_t)i * 16;

    u64 E[4][8];

    // ================= enc1, FIRST HALF (input pos 0..7 -> E[:][0..3]) ========
    u64 P0[8], P1[8];           // ch0 / ch1, positions 0..7 (packed A|B)
    {
        float4 a, b;
        a = xp[0]; b = xp[8];
        P0[0]=pk2(a.x,b.x); P0[1]=pk2(a.y,b.y); P0[2]=pk2(a.z,b.z); P0[3]=pk2(a.w,b.w);
        a = xp[1]; b = xp[9];
        P0[4]=pk2(a.x,b.x); P0[5]=pk2(a.y,b.y); P0[6]=pk2(a.z,b.z); P0[7]=pk2(a.w,b.w);
        a = xp[4]; b = xp[12];
        P1[0]=pk2(a.x,b.x); P1[1]=pk2(a.y,b.y); P1[2]=pk2(a.z,b.z); P1[3]=pk2(a.w,b.w);
        a = xp[5]; b = xp[13];
        P1[4]=pk2(a.x,b.x); P1[5]=pk2(a.y,b.y); P1[6]=pk2(a.z,b.z); P1[7]=pk2(a.w,b.w);
    }
    #pragma unroll
    for (int c = 0; c < 4; c++) {
        u64 w00 = s_we[c*6+0], w01 = s_we[c*6+1], w02 = s_we[c*6+2];
        u64 w10 = s_we[c*6+3], w11 = s_we[c*6+4], w12 = s_we[c*6+5];
        u64 b2 = s_be[c];
        #pragma unroll
        for (int l = 0; l < 4; l++) {
            int p = 2 * l;
            u64 a = b2;
            if (l > 0) { a = fma2(w00, P0[p-1], a); a = fma2(w10, P1[p-1], a); }
            a = fma2(w01, P0[p],   a); a = fma2(w11, P1[p],   a);
            a = fma2(w02, P0[p+1], a); a = fma2(w12, P1[p+1], a);
            E[c][l] = leaky2(a);
        }
    }
    u64 k0 = P0[7], k1 = P1[7];  // position-7 halo for second half

    // ================= enc1, SECOND HALF (input pos 8..15 -> E[:][4..7]) ======
    {
        float4 a, b;
        a = xp[2]; b = xp[10];
        P0[0]=pk2(a.x,b.x); P0[1]=pk2(a.y,b.y); P0[2]=pk2(a.z,b.z); P0[3]=pk2(a.w,b.w);
        a = xp[3]; b = xp[11];
        P0[4]=pk2(a.x,b.x); P0[5]=pk2(a.y,b.y); P0[6]=pk2(a.z,b.z); P0[7]=pk2(a.w,b.w);
        a = xp[6]; b = xp[14];
        P1[0]=pk2(a.x,b.x); P1[1]=pk2(a.y,b.y); P1[2]=pk2(a.z,b.z); P1[3]=pk2(a.w,b.w);
        a = xp[7]; b = xp[15];
        P1[4]=pk2(a.x,b.x); P1[5]=pk2(a.y,b.y); P1[6]=pk2(a.z,b.z); P1[7]=pk2(a.w,b.w);
    }
    #pragma unroll
    for (int c = 0; c < 4; c++) {
        u64 w00 = s_we[c*6+0], w01 = s_we[c*6+1], w02 = s_we[c*6+2];
        u64 w10 = s_we[c*6+3], w11 = s_we[c*6+4], w12 = s_we[c*6+5];
        u64 b2 = s_be[c];
        // l=4 uses halo pos7 + pos8,9
        {
            u64 a = b2;
            a = fma2(w00, k0,    a); a = fma2(w10, k1,    a);
            a = fma2(w01, P0[0], a); a = fma2(w11, P1[0], a);
            a = fma2(w02, P0[1], a); a = fma2(w12, P1[1], a);
            E[c][4] = leaky2(a);
        }
        #pragma unroll
        for (int l = 5; l < 8; l++) {
            int p = 2 * l - 8;   // index into P (pos 8+j)
            u64 a = b2;
            a = fma2(w00, P0[p-1], a); a = fma2(w10, P1[p-1], a);
            a = fma2(w01, P0[p],   a); a = fma2(w11, P1[p],   a);
            a = fma2(w02, P0[p+1], a); a = fma2(w12, P1[p+1], a);
            E[c][l] = leaky2(a);
        }
    }
    // P0/P1/k0/k1 dead past here.

    // ---- bneck: conv(C4->C8, k3, s2, p1) + leaky -> Bn[8][4] ----
    // weights loaded 3-at-a-time (6 regs live) instead of wk[12] preload
    u64 Bn[8][4];
    #pragma unroll
    for (int co = 0; co < 8; co++) {
        u64 acc0 = s_bb[co], acc1 = acc0, acc2 = acc0, acc3 = acc0;
        #pragma unroll
        for (int ci = 0; ci < 4; ci++) {
            u64 w0 = s_wb[co*12 + ci*3 + 0];
            u64 w1 = s_wb[co*12 + ci*3 + 1];
            u64 w2 = s_wb[co*12 + ci*3 + 2];
            acc0 = fma2(w1, E[ci][0], acc0); acc0 = fma2(w2, E[ci][1], acc0);
            acc1 = fma2(w0, E[ci][1], acc1); acc1 = fma2(w1, E[ci][2], acc1); acc1 = fma2(w2, E[ci][3], acc1);
            acc2 = fma2(w0, E[ci][3], acc2); acc2 = fma2(w1, E[ci][4], acc2); acc2 = fma2(w2, E[ci][5], acc2);
            acc3 = fma2(w0, E[ci][5], acc3); acc3 = fma2(w1, E[ci][6], acc3); acc3 = fma2(w2, E[ci][7], acc3);
        }
        Bn[co][0] = leaky2(acc0); Bn[co][1] = leaky2(acc1);
        Bn[co][2] = leaky2(acc2); Bn[co][3] = leaky2(acc3);
    }

    // ---- dec1: upsample2 + conv(C8->C4, k3, s1, p1) + leaky, skip in-place into E
    #pragma unroll
    for (int c = 0; c < 4; c++) {
        u64 acc[8];
        u64 b2 = s_bd[c];
        #pragma unroll
        for (int l = 0; l < 8; l++) acc[l] = b2;
        #pragma unroll
        for (int ci = 0; ci < 8; ci++) {
            const u64* wf = &s_wdf[(c*8 + ci) * 4];
            u64 w0 = wf[0], w2 = wf[1], w01 = wf[2], w12 = wf[3];
            u64 q0 = Bn[ci][0], q1 = Bn[ci][1], q2 = Bn[ci][2], q3 = Bn[ci][3];
            acc[0] = fma2(w12, q0, acc[0]);
            acc[1] = fma2(w01, q0, acc[1]); acc[1] = fma2(w2,  q1, acc[1]);
            acc[2] = fma2(w0,  q0, acc[2]); acc[2] = fma2(w12, q1, acc[2]);
            acc[3] = fma2(w01, q1, acc[3]); acc[3] = fma2(w2,  q2, acc[3]);
            acc[4] = fma2(w0,  q1, acc[4]); acc[4] = fma2(w12, q2, acc[4]);
            acc[5] = fma2(w01, q2, acc[5]); acc[5] = fma2(w2,  q3, acc[5]);
            acc[6] = fma2(w0,  q2, acc[6]); acc[6] = fma2(w12, q3, acc[6]);
            acc[7] = fma2(w01, q3, acc[7]);
        }
        #pragma unroll
        for (int l = 0; l < 8; l++)
            E[c][l] = add2(leaky2(acc[l]), E[c][l]);   // skip connection -> S
    }
    // Bn dead past here.

    // ---- out: upsample2 + conv(C4->C2, k3, s1, p1) + tanh; store per channel ----
    float4* op = out + (size_t)i * 16;
    #pragma unroll
    for (int c = 0; c < 2; c++) {
        u64 acc[16];
        u64 b2 = s_bo[c];
        #pragma unroll
        for (int l = 0; l < 16; l++) acc[l] = b2;
        #pragma unroll
        for (int ci = 0; ci < 4; ci++) {
            const u64* wf = &s_wof[(c*4 + ci) * 4];
            u64 w0 = wf[0], w2 = wf[1], w01 = wf[2], w12 = wf[3];
            acc[0]  = fma2(w12, E[ci][0], acc[0]);
            #pragma unroll
            for (int l = 1; l < 15; l++) {
                if ((l & 1) == 0) {
                    acc[l] = fma2(w0,  E[ci][l/2 - 1], acc[l]);
                    acc[l] = fma2(w12, E[ci][l/2],     acc[l]);
                } else {
                    acc[l] = fma2(w01, E[ci][(l-1)/2], acc[l]);
                    acc[l] = fma2(w2,  E[ci][(l+1)/2], acc[l]);
                }
            }
            acc[15] = fma2(w01, E[ci][7], acc[15]);
        }
        #pragma unroll
        for (int q = 0; q < 4; q++) {
            u64 t0 = tanh2(acc[q*4+0]);
            u64 t1 = tanh2(acc[q*4+1]);
            u64 t2 = tanh2(acc[q*4+2]);
            u64 t3 = tanh2(acc[q*4+3]);
            float4 va, vb;
            upk(t0, va.x, vb.x); upk(t1, va.y, vb.y);
            upk(t2, va.z, vb.z); upk(t3, va.w, vb.w);
            op[c*4 + q]     = va;   // sample A, channel-c quarter q
            op[8 + c*4 + q] = vb;   // sample B
        }
    }
}

extern "C" void kernel_launch(void* const* d_in, const int* in_sizes, int n_in,
                              void* d_out, int out_size) {
    const float4* x      = (const float4*)d_in[0];
    const float* w_enc1  = (const float*)d_in[1];
    const float* b_enc1  = (const float*)d_in[2];
    const float* w_bneck = (const float*)d_in[3];
    const float* b_bneck = (const float*)d_in[4];
    const float* w_dec1  = (const float*)d_in[5];
    const float* b_dec1  = (const float*)d_in[6];
    const float* w_out   = (const float*)d_in[7];
    const float* b_out   = (const float*)d_in[8];
    float4* out = (float4*)d_out;

    int B = in_sizes[0] / 32;        // samples
    int pairs = B / 2;               // two samples per thread
    int threads = 128;
    int blocks = (pairs + threads - 1) / threads;
    minigen_kernel<<<blocks, threads>>>(x, w_enc1, b_enc1, w_bneck, b_bneck,
                                        w_dec1, b_dec1, w_out, b_out, out);
}

// round 12
// speedup vs baseline: 1.2705x; 1.2705x over previous
#include <cuda_runtime.h>

typedef unsigned long long u64;

// ---- packed f32x2 helpers (sm_103a packed fp32 pipe) ----
__device__ __forceinline__ u64 pk2(float l, float h) {
    u64 r; asm("mov.b64 %0, {%1,%2};" : "=l"(r) : "f"(l), "f"(h)); return r;
}
__device__ __forceinline__ u64 pkb(float w) { return pk2(w, w); }
__device__ __forceinline__ void upk(u64 v, float& l, float& h) {
    asm("mov.b64 {%0,%1}, %2;" : "=f"(l), "=f"(h) : "l"(v));
}
__device__ __forceinline__ u64 fma2(u64 a, u64 b, u64 c) {
    u64 d; asm("fma.rn.f32x2 %0, %1, %2, %3;" : "=l"(d) : "l"(a), "l"(b), "l"(c)); return d;
}
__device__ __forceinline__ u64 add2(u64 a, u64 b) {
    u64 d; asm("add.rn.f32x2 %0, %1, %2;" : "=l"(d) : "l"(a), "l"(b)); return d;
}
__device__ __forceinline__ u64 mul2(u64 a, u64 b) {
    u64 d; asm("mul.rn.f32x2 %0, %1, %2;" : "=l"(d) : "l"(a), "l"(b)); return d;
}

#define KDUP(bits) ((((u64)(bits)) << 32) | (u64)(bits))
static constexpr u64 K06  = KDUP(0x3F19999Au);  // 0.6f
static constexpr u64 K04  = KDUP(0x3ECCCCCDu);  // 0.4f
static constexpr u64 KABS = 0x7FFFFFFF7FFFFFFFull;

// leaky_relu(x, 0.2) == 0.6*x + 0.4*|x|
__device__ __forceinline__ u64 leaky2(u64 v) {
    return fma2(v & KABS, K04, mul2(v, K06));
}

// HW tanh: 1 MUFU per scalar
__device__ __forceinline__ u64 tanh2(u64 v) {
    float l, h; upk(v, l, h);
    float tl, th;
    asm("tanh.approx.f32 %0, %1;" : "=f"(tl) : "f"(l));
    asm("tanh.approx.f32 %0, %1;" : "=f"(th) : "f"(h));
    return pk2(tl, th);
}

// 128-bit shared load of a u64 pair (requires 16B-aligned index)
__device__ __forceinline__ ulonglong2 lds2(const u64* p) {
    return *reinterpret_cast<const ulonglong2*>(p);
}

__global__ void __launch_bounds__(128)
minigen_kernel(const float4* __restrict__ x,
               const float* __restrict__ w_enc1, const float* __restrict__ b_enc1,
               const float* __restrict__ w_bneck, const float* __restrict__ b_bneck,
               const float* __restrict__ w_dec1, const float* __restrict__ b_dec1,
               const float* __restrict__ w_out,  const float* __restrict__ b_out,
               float4* __restrict__ out)
{
    // all weights pre-duplicated as u64 packed pairs, laid out for 128-bit LDS:
    // s_we : per channel c: 8 slots {w00,w01,w02,w10,w11,w12,bias,pad}
    // s_wb : per channel co: 16 slots {w[0..11], bias, pad,pad,pad}
    // s_wdf: per (c,ci): 4 slots {w0, w2, w0+w1, w1+w2}  (stride 32B, aligned)
    // s_wof: same folding for out layer
    __shared__ __align__(16) u64 s_we[32];
    __shared__ __align__(16) u64 s_wb[128];
    __shared__ __align__(16) u64 s_wdf[128];
    __shared__ __align__(16) u64 s_wof[32];
    __shared__ __align__(16) u64 s_bd[4], s_bo[2];

    int t = threadIdx.x;
    if (t < 4) {   // enc1: channel t
        #pragma unroll
        for (int j = 0; j < 6; j++) s_we[t*8 + j] = pkb(w_enc1[t*6 + j]);
        s_we[t*8 + 6] = pkb(b_enc1[t]);
        s_we[t*8 + 7] = 0;
        s_bd[t] = pkb(b_dec1[t]);
    }
    if (t >= 8 && t < 16) {   // bneck: channel co = t-8
        int co = t - 8;
        #pragma unroll
        for (int j = 0; j < 12; j++) s_wb[co*16 + j] = pkb(w_bneck[co*12 + j]);
        s_wb[co*16 + 12] = pkb(b_bneck[co]);
        s_wb[co*16 + 13] = 0; s_wb[co*16 + 14] = 0; s_wb[co*16 + 15] = 0;
    }
    if (t >= 32 && t < 64) {  // dec1 fold: pair index p = t-32 = c*8+ci
        int p = t - 32;
        float w0 = w_dec1[p*3], w1 = w_dec1[p*3+1], w2 = w_dec1[p*3+2];
        s_wdf[p*4+0] = pkb(w0);      s_wdf[p*4+1] = pkb(w2);
        s_wdf[p*4+2] = pkb(w0 + w1); s_wdf[p*4+3] = pkb(w1 + w2);
    }
    if (t >= 64 && t < 72) {  // out fold: pair index p = t-64 = c*4+ci
        int p = t - 64;
        float w0 = w_out[p*3], w1 = w_out[p*3+1], w2 = w_out[p*3+2];
        s_wof[p*4+0] = pkb(w0);      s_wof[p*4+1] = pkb(w2);
        s_wof[p*4+2] = pkb(w0 + w1); s_wof[p*4+3] = pkb(w1 + w2);
    }
    if (t >= 72 && t < 74) s_bo[t - 72] = pkb(b_out[t - 72]);
    __syncthreads();

    int i = blockIdx.x * blockDim.x + threadIdx.x;   // sample-pair index

    // ---- load 2 samples (2 x 128B contiguous lines), pack across samples ----
    u64 X2[32];
    {
        const float4* xp = x + (size_t)i * 16;
        float A[32], Bv[32];
        #pragma unroll
        for (int q = 0; q < 8; q++) {
            float4 va = xp[q];
            A[q*4+0] = va.x; A[q*4+1] = va.y; A[q*4+2] = va.z; A[q*4+3] = va.w;
        }
        #pragma unroll
        for (int q = 0; q < 8; q++) {
            float4 vb = xp[8 + q];
            Bv[q*4+0] = vb.x; Bv[q*4+1] = vb.y; Bv[q*4+2] = vb.z; Bv[q*4+3] = vb.w;
        }
        #pragma unroll
        for (int j = 0; j < 32; j++) X2[j] = pk2(A[j], Bv[j]);
    }

    // ---- enc1: conv(C2->C4, k3, s2, p1) + leaky -> E[4][8] ----
    u64 E[4][8];
    #pragma unroll
    for (int c = 0; c < 4; c++) {
        ulonglong2 q0 = lds2(&s_we[c*8 + 0]);   // w00, w01
        ulonglong2 q1 = lds2(&s_we[c*8 + 2]);   // w02, w10
        ulonglong2 q2 = lds2(&s_we[c*8 + 4]);   // w11, w12
        u64 w00 = q0.x, w01 = q0.y, w02 = q1.x;
        u64 w10 = q1.y, w11 = q2.x, w12 = q2.y;
        u64 b2 = s_we[c*8 + 6];
        #pragma unroll
        for (int l = 0; l < 8; l++) {
            int p = 2 * l;
            u64 a = b2;
            if (l > 0) { a = fma2(w00, X2[p-1], a); a = fma2(w10, X2[16+p-1], a); }
            a = fma2(w01, X2[p],     a); a = fma2(w11, X2[16+p],   a);
            a = fma2(w02, X2[p+1],   a); a = fma2(w12, X2[16+p+1], a);
            E[c][l] = leaky2(a);
        }
    }
    // X2 dead past here.

    // ---- bneck: conv(C4->C8, k3, s2, p1) + leaky -> Bn[8][4] ----
    u64 Bn[8][4];
    #pragma unroll
    for (int co = 0; co < 8; co++) {
        u64 wk[12];
        #pragma unroll
        for (int j = 0; j < 6; j++) {
            ulonglong2 q = lds2(&s_wb[co*16 + j*2]);
            wk[j*2] = q.x; wk[j*2+1] = q.y;
        }
        u64 b2 = s_wb[co*16 + 12];
        #pragma unroll
        for (int l = 0; l < 4; l++) {
            int p = 2 * l;
            u64 a = b2;
            #pragma unroll
            for (int ci = 0; ci < 4; ci++) {
                if (l > 0) a = fma2(wk[ci*3+0], E[ci][p-1], a);
                a = fma2(wk[ci*3+1], E[ci][p],   a);
                a = fma2(wk[ci*3+2], E[ci][p+1], a);
            }
            Bn[co][l] = leaky2(a);
        }
    }

    // ---- dec1: upsample2 + conv(C8->C4, k3, s1, p1) + leaky, skip in-place into E
    #pragma unroll
    for (int c = 0; c < 4; c++) {
        u64 acc[8];
        u64 b2 = s_bd[c];
        #pragma unroll
        for (int l = 0; l < 8; l++) acc[l] = b2;
        #pragma unroll
        for (int ci = 0; ci < 8; ci++) {
            ulonglong2 qa = lds2(&s_wdf[(c*8 + ci)*4 + 0]);  // w0, w2
            ulonglong2 qb = lds2(&s_wdf[(c*8 + ci)*4 + 2]);  // w01, w12
            u64 w0 = qa.x, w2 = qa.y, w01 = qb.x, w12 = qb.y;
            u64 q0 = Bn[ci][0], q1 = Bn[ci][1], q2 = Bn[ci][2], q3 = Bn[ci][3];
            acc[0] = fma2(w12, q0, acc[0]);
            acc[1] = fma2(w01, q0, acc[1]); acc[1] = fma2(w2,  q1, acc[1]);
            acc[2] = fma2(w0,  q0, acc[2]); acc[2] = fma2(w12, q1, acc[2]);
            acc[3] = fma2(w01, q1, acc[3]); acc[3] = fma2(w2,  q2, acc[3]);
            acc[4] = fma2(w0,  q1, acc[4]); acc[4] = fma2(w12, q2, acc[4]);
            acc[5] = fma2(w01, q2, acc[5]); acc[5] = fma2(w2,  q3, acc[5]);
            acc[6] = fma2(w0,  q2, acc[6]); acc[6] = fma2(w12, q3, acc[6]);
            acc[7] = fma2(w01, q3, acc[7]);
        }
        #pragma unroll
        for (int l = 0; l < 8; l++)
            E[c][l] = add2(leaky2(acc[l]), E[c][l]);   // skip connection -> S
    }
    // Bn dead past here.

    // ---- out: upsample2 + conv(C4->C2, k3, s1, p1) + tanh; store per channel ----
    float4* op = out + (size_t)i * 16;
    #pragma unroll
    for (int c = 0; c < 2; c++) {
        u64 acc[16];
        u64 b2 = s_bo[c];
        #pragma unroll
        for (int l = 0; l < 16; l++) acc[l] = b2;
        #pragma unroll
        for (int ci = 0; ci < 4; ci++) {
            ulonglong2 qa = lds2(&s_wof[(c*4 + ci)*4 + 0]);  // w0, w2
            ulonglong2 qb = lds2(&s_wof[(c*4 + ci)*4 + 2]);  // w01, w12
            u64 w0 = qa.x, w2 = qa.y, w01 = qb.x, w12 = qb.y;
            acc[0]  = fma2(w12, E[ci][0], acc[0]);
            #pragma unroll
            for (int l = 1; l < 15; l++) {
                if ((l & 1) == 0) {
                    acc[l] = fma2(w0,  E[ci][l/2 - 1], acc[l]);
                    acc[l] = fma2(w12, E[ci][l/2],     acc[l]);
                } else {
                    acc[l] = fma2(w01, E[ci][(l-1)/2], acc[l]);
                    acc[l] = fma2(w2,  E[ci][(l+1)/2], acc[l]);
                }
            }
            acc[15] = fma2(w01, E[ci][7], acc[15]);
        }
        #pragma unroll
        for (int q = 0; q < 4; q++) {
            u64 t0 = tanh2(acc[q*4+0]);
            u64 t1 = tanh2(acc[q*4+1]);
            u64 t2 = tanh2(acc[q*4+2]);
            u64 t3 = tanh2(acc[q*4+3]);
            float4 va, vb;
            upk(t0, va.x, vb.x); upk(t1, va.y, vb.y);
            upk(t2, va.z, vb.z); upk(t3, va.w, vb.w);
            op[c*4 + q]     = va;   // sample A, channel-c quarter q
            op[8 + c*4 + q] = vb;   // sample B
        }
    }
}

extern "C" void kernel_launch(void* const* d_in, const int* in_sizes, int n_in,
                              void* d_out, int out_size) {
    const float4* x      = (const float4*)d_in[0];
    const float* w_enc1  = (const float*)d_in[1];
    const float* b_enc1  = (const float*)d_in[2];
    const float* w_bneck = (const float*)d_in[3];
    const float* b_bneck = (const float*)d_in[4];
    const float* w_dec1  = (const float*)d_in[5];
    const float* b_dec1  = (const float*)d_in[6];
    const float* w_out   = (const float*)d_in[7];
    const float* b_out   = (const float*)d_in[8];
    float4* out = (float4*)d_out;

    int B = in_sizes[0] / 32;        // samples
    int pairs = B / 2;               // two samples per thread
    int threads = 128;
    int blocks = (pairs + threads - 1) / threads;
    minigen_kernel<<<blocks, threads>>>(x, w_enc1, b_enc1, w_bneck, b_bneck,
                                        w_dec1, b_dec1, w_out, b_out, out);
}